// round 1
// baseline (speedup 1.0000x reference)
#include <cuda_runtime.h>
#include <cuda_bf16.h>

#define NMAX 100000
#define CMAX 128

// Scratch buffers (allocation-free rule: __device__ globals)
__device__ float d_B1[(size_t)NMAX * CMAX];
__device__ float d_B2[(size_t)NMAX * CMAX];
__device__ float d_B3[(size_t)NMAX * CMAX];
__device__ float d_deg[NMAX];
__device__ float d_dinv[NMAX];
__device__ float d_partial[256 * 64];

// ---------------- degree / dinv ----------------
__global__ void k_deg_init(int N) {
    int i = blockIdx.x * blockDim.x + threadIdx.x;
    if (i < N) d_deg[i] = 1.0f;  // self-loop
}
__global__ void k_deg_add(const int* __restrict__ dst, int E) {
    int i = blockIdx.x * blockDim.x + threadIdx.x;
    if (i < E) atomicAdd(&d_deg[dst[i]], 1.0f);
}
__global__ void k_dinv(int N) {
    int i = blockIdx.x * blockDim.x + threadIdx.x;
    if (i < N) d_dinv[i] = rsqrtf(d_deg[i]);
}

// ---------------- fused GEMM ----------------
// Computes g[row][c] = dinv[row] * (A'[row] @ W)[c], and buf = g (self-loop init).
// If PRE: A'[row][k] = relu(dinv[row]*Ain[row][k] + bpre[k])  (fused finalize of
// the previous layer's aggregation). Else A' = Ain directly.
template <int COLS, int TROWS, bool PRE>
__global__ void __launch_bounds__(256, 2)
k_gemm(const float* __restrict__ Ain, const float* __restrict__ W,
       const float* __restrict__ bpre, float* __restrict__ g,
       float* __restrict__ buf, int N)
{
    extern __shared__ float sm[];
    constexpr int RS = TROWS + 4;            // row stride for Xs (mult of 4 for LDS.128)
    float* Xs = sm;                          // [128][RS]  (k-major, transposed tile)
    float* Ws = sm + 128 * RS;               // [128][COLS]
    const int tid = threadIdx.x;
    const int base = blockIdx.x * TROWS;

    // Load W into smem
    for (int i = tid; i < 128 * COLS / 4; i += 256)
        ((float4*)Ws)[i] = __ldg((const float4*)W + i);

    // Load A tile (transposed into Xs). r-fast mapping: smem stores conflict-free.
    for (int i = tid; i < TROWS * 32; i += 256) {
        int r  = i % TROWS;
        int k4 = i / TROWS;
        int row = base + r;
        float4 v = make_float4(0.f, 0.f, 0.f, 0.f);
        if (row < N) {
            v = __ldg((const float4*)(Ain + (size_t)row * 128) + k4);
            if (PRE) {
                float dv = d_dinv[row];
                float4 b = __ldg((const float4*)bpre + k4);
                v.x = fmaxf(fmaf(v.x, dv, b.x), 0.f);
                v.y = fmaxf(fmaf(v.y, dv, b.y), 0.f);
                v.z = fmaxf(fmaf(v.z, dv, b.z), 0.f);
                v.w = fmaxf(fmaf(v.w, dv, b.w), 0.f);
            }
        }
        int k = k4 * 4;
        Xs[(k + 0) * RS + r] = v.x;
        Xs[(k + 1) * RS + r] = v.y;
        Xs[(k + 2) * RS + r] = v.z;
        Xs[(k + 3) * RS + r] = v.w;
    }
    __syncthreads();

    constexpr int CG = COLS / 4;             // col groups of 4
    const int cg = tid % CG;
    const int rg = tid / CG;                 // (256/CG)*8 == TROWS rows covered

    float acc[8][4];
#pragma unroll
    for (int r = 0; r < 8; r++)
#pragma unroll
        for (int c = 0; c < 4; c++) acc[r][c] = 0.f;

#pragma unroll 4
    for (int k = 0; k < 128; k++) {
        float4 xa = *(const float4*)&Xs[k * RS + rg * 8];
        float4 xb = *(const float4*)&Xs[k * RS + rg * 8 + 4];
        float4 w  = *(const float4*)&Ws[k * COLS + cg * 4];
        float xr[8] = {xa.x, xa.y, xa.z, xa.w, xb.x, xb.y, xb.z, xb.w};
        float wc[4] = {w.x, w.y, w.z, w.w};
#pragma unroll
        for (int r = 0; r < 8; r++)
#pragma unroll
            for (int c = 0; c < 4; c++) acc[r][c] = fmaf(xr[r], wc[c], acc[r][c]);
    }

    // Epilogue: scale by dinv[row]; write g and buf (= self-loop init of agg)
#pragma unroll
    for (int r = 0; r < 8; r++) {
        int row = base + rg * 8 + r;
        if (row < N) {
            float dv = d_dinv[row];
            float4 o = make_float4(acc[r][0] * dv, acc[r][1] * dv,
                                   acc[r][2] * dv, acc[r][3] * dv);
            *(float4*)(g   + (size_t)row * COLS + cg * 4) = o;
            *(float4*)(buf + (size_t)row * COLS + cg * 4) = o;
        }
    }
}

// ---------------- edge scatter: buf[dst] += g[src] ----------------
template <int C>
__global__ void k_scatter(const int* __restrict__ src, const int* __restrict__ dst,
                          const float* __restrict__ g, float* __restrict__ buf, int E)
{
    constexpr int QPE = C / 4;               // quads per edge
    int t = blockIdx.x * blockDim.x + threadIdx.x;
    int e = t / QPE;
    int q = t % QPE;
    if (e >= E) return;
    int s = __ldg(src + e);
    int d = __ldg(dst + e);
    float4 v = __ldg((const float4*)(g + (size_t)s * C) + q);
    float* p = buf + (size_t)d * C + q * 4;
    asm volatile("red.global.add.v4.f32 [%0], {%1,%2,%3,%4};"
                 :: "l"(p), "f"(v.x), "f"(v.y), "f"(v.z), "f"(v.w) : "memory");
}

// ---------------- min pool (two stage) ----------------
__global__ void k_minpool1(const float* __restrict__ buf, int N) {
    int c  = threadIdx.x & 63;
    int rg = threadIdx.x >> 6;               // 0..3
    float m = 3.402823466e38f;
    for (int i = blockIdx.x * 4 + rg; i < N; i += gridDim.x * 4)
        m = fminf(m, d_dinv[i] * buf[(size_t)i * 64 + c]);
    __shared__ float s[256];
    s[threadIdx.x] = m;
    __syncthreads();
    if (rg == 0) {
        m = fminf(fminf(s[c], s[64 + c]), fminf(s[128 + c], s[192 + c]));
        d_partial[blockIdx.x * 64 + c] = m;
    }
}
__global__ void k_minpool2(const float* __restrict__ b3, float* __restrict__ out, int nblk) {
    int c = threadIdx.x;
    float m = 3.402823466e38f;
    for (int i = 0; i < nblk; i++) m = fminf(m, d_partial[i * 64 + c]);
    out[c] = m + b3[c];
}

extern "C" void kernel_launch(void* const* d_in, const int* in_sizes, int n_in,
                              void* d_out, int out_size)
{
    const float* x  = (const float*)d_in[0];
    const int*   ei = (const int*)d_in[1];
    const float* W1 = (const float*)d_in[2];
    const float* b1 = (const float*)d_in[3];
    const float* W2 = (const float*)d_in[4];
    const float* b2 = (const float*)d_in[5];
    const float* W3 = (const float*)d_in[6];
    const float* b3 = (const float*)d_in[7];
    float* out = (float*)d_out;

    int N = in_sizes[0] / 128;
    int E = in_sizes[1] / 2;
    const int* src = ei;
    const int* dst = ei + E;

    float *B1, *B2, *B3;
    cudaGetSymbolAddress((void**)&B1, d_B1);
    cudaGetSymbolAddress((void**)&B2, d_B2);
    cudaGetSymbolAddress((void**)&B3, d_B3);

    const int smemA = (128 * (64 + 4) + 128 * 128) * 4;   // k_gemm<128,64,*>
    const int smemB = (128 * (128 + 4) + 128 * 64) * 4;   // k_gemm<64,128,true>
    cudaFuncSetAttribute(k_gemm<128, 64, false>, cudaFuncAttributeMaxDynamicSharedMemorySize, smemA);
    cudaFuncSetAttribute(k_gemm<128, 64, true>,  cudaFuncAttributeMaxDynamicSharedMemorySize, smemA);
    cudaFuncSetAttribute(k_gemm<64, 128, true>,  cudaFuncAttributeMaxDynamicSharedMemorySize, smemB);

    // degrees
    k_deg_init<<<(N + 255) / 256, 256>>>(N);
    k_deg_add<<<(E + 255) / 256, 256>>>(dst, E);
    k_dinv<<<(N + 255) / 256, 256>>>(N);

    // Layer 1: A = x
    k_gemm<128, 64, false><<<(N + 63) / 64, 256, smemA>>>(x, W1, nullptr, B1, B2, N);
    k_scatter<128><<<(E * 32 + 255) / 256, 256>>>(src, dst, B1, B2, E);

    // Layer 2: A = relu(dinv*B2 + b1)
    k_gemm<128, 64, true><<<(N + 63) / 64, 256, smemA>>>(B2, W2, b1, B1, B3, N);
    k_scatter<128><<<(E * 32 + 255) / 256, 256>>>(src, dst, B1, B3, E);

    // Layer 3: A = relu(dinv*B3 + b2), 64 output cols
    k_gemm<64, 128, true><<<(N + 127) / 128, 256, smemB>>>(B3, W3, b2, B1, B2, N);
    k_scatter<64><<<(E * 16 + 255) / 256, 256>>>(src, dst, B1, B2, E);

    // min-pool with dinv + b3 fused
    k_minpool1<<<256, 256>>>(B2, N);
    k_minpool2<<<1, 64>>>(b3, out, 256);
}

// round 2
// speedup vs baseline: 1.6526x; 1.6526x over previous
#include <cuda_runtime.h>
#include <cuda_bf16.h>

#define NMAX 100000
#define EMAX 1600000
#define CMAX 128

// Scratch (__device__ globals: allocation-free rule)
__device__ float d_B1[(size_t)NMAX * CMAX];
__device__ float d_B2[(size_t)NMAX * CMAX];
__device__ float d_B3[(size_t)NMAX * CMAX];
__device__ float d_dinv[NMAX];
__device__ int   d_cnt[NMAX];
__device__ int   d_cur[NMAX];
__device__ int   d_off[NMAX + 1];
__device__ int   d_csr[EMAX];
__device__ int   d_blk[128];
__device__ int   d_blk2[128];
__device__ float d_partial[256 * 64];

#define FMA2(d, a, b, c) \
    asm("fma.rn.f32x2 %0, %1, %2, %3;" : "=l"(d) : "l"(a), "l"(b), "l"(c))
#define PACK2(d, x) \
    asm("mov.b64 %0, {%1, %1};" : "=l"(d) : "f"(x))
#define UNPACK2(lo, hi, v) \
    asm("mov.b64 {%0, %1}, %2;" : "=f"(lo), "=f"(hi) : "l"(v))

// ================= CSR build =================
__global__ void k_hist(const int* __restrict__ dst, int E) {
    int i = blockIdx.x * blockDim.x + threadIdx.x;
    if (i < E) atomicAdd(&d_cnt[dst[i]], 1);
}

// block scans 1024 counts (4/thread), writes per-element exclusive offsets + block total
__global__ void k_scan1(int N) {
    __shared__ int sh[256];
    int t = threadIdx.x;
    int base = blockIdx.x * 1024 + t * 4;
    int c0 = 0, c1 = 0, c2 = 0, c3 = 0;
    if (base + 3 < N) {
        int4 v = *(const int4*)&d_cnt[base];
        c0 = v.x; c1 = v.y; c2 = v.z; c3 = v.w;
    } else {
        if (base + 0 < N) c0 = d_cnt[base + 0];
        if (base + 1 < N) c1 = d_cnt[base + 1];
        if (base + 2 < N) c2 = d_cnt[base + 2];
        if (base + 3 < N) c3 = d_cnt[base + 3];
    }
    int s = c0 + c1 + c2 + c3;
    sh[t] = s;
    __syncthreads();
    for (int d = 1; d < 256; d <<= 1) {
        int v = (t >= d) ? sh[t - d] : 0;
        __syncthreads();
        sh[t] += v;
        __syncthreads();
    }
    int excl = sh[t] - s;
    if (base + 0 < N) d_off[base + 0] = excl;
    if (base + 1 < N) d_off[base + 1] = excl + c0;
    if (base + 2 < N) d_off[base + 2] = excl + c0 + c1;
    if (base + 3 < N) d_off[base + 3] = excl + c0 + c1 + c2;
    if (t == 255) d_blk[blockIdx.x] = sh[255];
}

__global__ void k_scan2(int nblk) {
    __shared__ int sh[128];
    int t = threadIdx.x;
    int v = (t < nblk) ? d_blk[t] : 0;
    sh[t] = v;
    __syncthreads();
    for (int d = 1; d < 128; d <<= 1) {
        int u = (t >= d) ? sh[t - d] : 0;
        __syncthreads();
        sh[t] += u;
        __syncthreads();
    }
    d_blk2[t] = sh[t] - v;
}

__global__ void k_scan3(int N, int E) {
    int i = blockIdx.x * blockDim.x + threadIdx.x;
    if (i < N) {
        d_off[i] += d_blk2[i >> 10];
        d_dinv[i] = rsqrtf((float)d_cnt[i] + 1.0f);  // +1 self-loop
        d_cur[i] = 0;
    }
    if (i == 0) d_off[N] = E;
}

__global__ void k_fill(const int* __restrict__ src, const int* __restrict__ dst, int E) {
    int i = blockIdx.x * blockDim.x + threadIdx.x;
    if (i >= E) return;
    int d = dst[i];
    int p = atomicAdd(&d_cur[d], 1);
    d_csr[d_off[d] + p] = src[i];
}

// ================= GEMM: g[row] = dinv[row] * (A[row] @ W), f32x2 packed =================
// threads = (COLS/8)*(TROWS/8) = 128 ; each thread computes an 8x8 tile.
template <int COLS, int TROWS>
__global__ void __launch_bounds__(128)
k_gemm(const float* __restrict__ A, const float* __restrict__ W,
       float* __restrict__ g, int N)
{
    extern __shared__ float sm[];
    constexpr int RS = TROWS + 4;
    float* Xs = sm;               // [128][RS] transposed (k-major, row-fast)
    float* Ws = sm + 128 * RS;    // [128][COLS]
    constexpr int CG = COLS / 8;
    const int tid = threadIdx.x;
    const int cg = tid % CG;
    const int rg = tid / CG;
    const int base = blockIdx.x * TROWS;

    for (int i = tid; i < 128 * COLS / 4; i += 128)
        ((float4*)Ws)[i] = __ldg((const float4*)W + i);

    for (int i = tid; i < TROWS * 32; i += 128) {
        int r = i % TROWS;
        int k4 = i / TROWS;
        int row = base + r;
        float4 v = make_float4(0.f, 0.f, 0.f, 0.f);
        if (row < N) v = __ldg((const float4*)(A + (size_t)row * 128) + k4);
        int k = k4 * 4;
        Xs[(k + 0) * RS + r] = v.x;
        Xs[(k + 1) * RS + r] = v.y;
        Xs[(k + 2) * RS + r] = v.z;
        Xs[(k + 3) * RS + r] = v.w;
    }
    __syncthreads();

    unsigned long long acc[8][4];
#pragma unroll
    for (int r = 0; r < 8; r++)
#pragma unroll
        for (int c = 0; c < 4; c++) acc[r][c] = 0ull;

#pragma unroll 4
    for (int k = 0; k < 128; k++) {
        float4 xa = *(const float4*)&Xs[k * RS + rg * 8];
        float4 xb = *(const float4*)&Xs[k * RS + rg * 8 + 4];
        float xr[8] = {xa.x, xa.y, xa.z, xa.w, xb.x, xb.y, xb.z, xb.w};
        unsigned long long x2[8];
#pragma unroll
        for (int r = 0; r < 8; r++) PACK2(x2[r], xr[r]);
        ulonglong2 wA = *(const ulonglong2*)&Ws[k * COLS + cg * 8];
        ulonglong2 wB = *(const ulonglong2*)&Ws[k * COLS + cg * 8 + 4];
        unsigned long long w2[4] = {wA.x, wA.y, wB.x, wB.y};
#pragma unroll
        for (int r = 0; r < 8; r++)
#pragma unroll
            for (int c = 0; c < 4; c++) FMA2(acc[r][c], x2[r], w2[c], acc[r][c]);
    }

#pragma unroll
    for (int r = 0; r < 8; r++) {
        int row = base + rg * 8 + r;
        if (row < N) {
            float dv = d_dinv[row];
            float o[8];
#pragma unroll
            for (int c = 0; c < 4; c++) {
                float lo, hi;
                UNPACK2(lo, hi, acc[r][c]);
                o[2 * c] = lo * dv;
                o[2 * c + 1] = hi * dv;
            }
            float* p = g + (size_t)row * COLS + cg * 8;
            *(float4*)p = make_float4(o[0], o[1], o[2], o[3]);
            *(float4*)(p + 4) = make_float4(o[4], o[5], o[6], o[7]);
        }
    }
}

// ================= CSR aggregate: out[n] = post(dinv[n] * (g[n] + sum g[nbr])) =========
template <int TPN, bool RELU>
__global__ void k_agg(const float* __restrict__ g, const float* __restrict__ bias,
                      float* __restrict__ out, int N)
{
    int idx = blockIdx.x * blockDim.x + threadIdx.x;
    int node = idx / TPN;
    int lane = idx % TPN;
    if (node >= N) return;
    const float4* gp = (const float4*)g;
    size_t rb = (size_t)node * TPN;
    float4 acc = __ldg(&gp[rb + lane]);   // self-loop term
    int s = d_off[node], e = d_off[node + 1];
    int j = s;
    for (; j + 4 <= e; j += 4) {
        int n0 = d_csr[j], n1 = d_csr[j + 1], n2 = d_csr[j + 2], n3 = d_csr[j + 3];
        float4 v0 = __ldg(&gp[(size_t)n0 * TPN + lane]);
        float4 v1 = __ldg(&gp[(size_t)n1 * TPN + lane]);
        float4 v2 = __ldg(&gp[(size_t)n2 * TPN + lane]);
        float4 v3 = __ldg(&gp[(size_t)n3 * TPN + lane]);
        acc.x += (v0.x + v1.x) + (v2.x + v3.x);
        acc.y += (v0.y + v1.y) + (v2.y + v3.y);
        acc.z += (v0.z + v1.z) + (v2.z + v3.z);
        acc.w += (v0.w + v1.w) + (v2.w + v3.w);
    }
    for (; j < e; j++) {
        float4 v = __ldg(&gp[(size_t)d_csr[j] * TPN + lane]);
        acc.x += v.x; acc.y += v.y; acc.z += v.z; acc.w += v.w;
    }
    float dv = d_dinv[node];
    float4 r;
    if (RELU) {
        float4 b = __ldg((const float4*)bias + lane);
        r.x = fmaxf(fmaf(acc.x, dv, b.x), 0.f);
        r.y = fmaxf(fmaf(acc.y, dv, b.y), 0.f);
        r.z = fmaxf(fmaf(acc.z, dv, b.z), 0.f);
        r.w = fmaxf(fmaf(acc.w, dv, b.w), 0.f);
    } else {
        r.x = acc.x * dv; r.y = acc.y * dv; r.z = acc.z * dv; r.w = acc.w * dv;
    }
    ((float4*)out)[rb + lane] = r;
}

// ================= min pool =================
__global__ void k_minpool1(const float* __restrict__ buf, int N) {
    int c = threadIdx.x & 63;
    int rg = threadIdx.x >> 6;
    float m = 3.402823466e38f;
    for (int i = blockIdx.x * 4 + rg; i < N; i += gridDim.x * 4)
        m = fminf(m, buf[(size_t)i * 64 + c]);
    __shared__ float s[256];
    s[threadIdx.x] = m;
    __syncthreads();
    if (rg == 0) {
        m = fminf(fminf(s[c], s[64 + c]), fminf(s[128 + c], s[192 + c]));
        d_partial[blockIdx.x * 64 + c] = m;
    }
}
__global__ void k_minpool2(const float* __restrict__ b3, float* __restrict__ out, int nblk) {
    int c = threadIdx.x;
    float m = 3.402823466e38f;
    for (int i = 0; i < nblk; i++) m = fminf(m, d_partial[i * 64 + c]);
    out[c] = m + b3[c];
}

extern "C" void kernel_launch(void* const* d_in, const int* in_sizes, int n_in,
                              void* d_out, int out_size)
{
    const float* x  = (const float*)d_in[0];
    const int*   ei = (const int*)d_in[1];
    const float* W1 = (const float*)d_in[2];
    const float* b1 = (const float*)d_in[3];
    const float* W2 = (const float*)d_in[4];
    const float* b2 = (const float*)d_in[5];
    const float* W3 = (const float*)d_in[6];
    const float* b3 = (const float*)d_in[7];
    float* out = (float*)d_out;

    int N = in_sizes[0] / 128;
    int E = in_sizes[1] / 2;
    const int* src = ei;
    const int* dst = ei + E;

    float *B1, *B2, *B3;
    void* cntp;
    cudaGetSymbolAddress((void**)&B1, d_B1);
    cudaGetSymbolAddress((void**)&B2, d_B2);
    cudaGetSymbolAddress((void**)&B3, d_B3);
    cudaGetSymbolAddress(&cntp, d_cnt);

    const int smem = (128 * (64 + 4) + 128 * 128) * 4;   // == (128*(128+4)+128*64)*4
    cudaFuncSetAttribute(k_gemm<128, 64>, cudaFuncAttributeMaxDynamicSharedMemorySize, smem);
    cudaFuncSetAttribute(k_gemm<64, 128>, cudaFuncAttributeMaxDynamicSharedMemorySize, smem);

    // CSR build (per launch; also produces dinv)
    cudaMemsetAsync(cntp, 0, (size_t)N * sizeof(int));
    k_hist<<<(E + 255) / 256, 256>>>(dst, E);
    int nblk = (N + 1023) / 1024;
    k_scan1<<<nblk, 256>>>(N);
    k_scan2<<<1, 128>>>(nblk);
    k_scan3<<<(N + 255) / 256, 256>>>(N, E);
    k_fill<<<(E + 255) / 256, 256>>>(src, dst, E);

    // Layer 1
    k_gemm<128, 64><<<(N + 63) / 64, 128, smem>>>(x, W1, B1, N);
    k_agg<32, true><<<(N * 32 + 255) / 256, 256>>>(B1, b1, B2, N);
    // Layer 2
    k_gemm<128, 64><<<(N + 63) / 64, 128, smem>>>(B2, W2, B1, N);
    k_agg<32, true><<<(N * 32 + 255) / 256, 256>>>(B1, b2, B3, N);
    // Layer 3 (64 cols)
    k_gemm<64, 128><<<(N + 127) / 128, 128, smem>>>(B3, W3, B1, N);
    k_agg<16, false><<<(N * 16 + 255) / 256, 256>>>(B1, nullptr, B2, N);

    k_minpool1<<<256, 256>>>(B2, N);
    k_minpool2<<<1, 64>>>(b3, out, 256);
}